// round 13
// baseline (speedup 1.0000x reference)
#include <cuda_runtime.h>
#include <cuda_fp16.h>
#include <cstdint>

// HardwareVMM: out = sum_{c<32} Q(x_chunk @ W_chunk^T) + bias. B=8192,K=N=4096.
// R13: fp16-hi + int8-lo packed operands (3B/elem), in-SMEM expansion warps,
// tcgen05 3-term fp16 MMA, BM=256/BN=128/KSUB=32, 3-stage ring, TMEM ping-pong.

#if defined(__CUDA_ARCH__) && defined(__CUDA_ARCH_FEAT_SM103_ALL)
#define TC_ON 1
#else
#define TC_ON 0
#endif

#define K_DIM 4096
#define N_DIM 4096
#define BN 128
#define NSTAGE 3
#define TILE_PK 12288            // [hi fp16 SW64 8192 | q int8 4096]
#define OFF_A0L 36864
#define OFF_A1L 45056
#define OFF_BL  53248
#define STAGE   61440            // A0[hi|q] A1[hi|q] B[hi|q] | A0l A1l Bl
#define RAW_TX  36864
#define NSS 128
#define NCHUNK 32
#define THREADS 704              // 16 epi + mma + prod + 4 exp warps
#define MMA_WARP 16
#define PROD_WARP 17
#define IDESC 0x8200010u         // f32 acc, fp16 x fp16, M=128, N=128
#define DYN_BYTES (NSTAGE*STAGE + 1024)
#define MAGIC 12582912.0f
#define KB_TILES 128

__device__ __align__(128) uint8_t g_xpack[(size_t)64*128*TILE_PK];
__device__ __align__(128) uint8_t g_wpack[(size_t)32*128*TILE_PK];

__device__ __forceinline__ uint32_t smem_u32(const void* p){return (uint32_t)__cvta_generic_to_shared(p);}
__device__ __forceinline__ uint32_t swz64(uint32_t o){return o ^ ((o>>3)&0x30);}
__device__ __forceinline__ unsigned long long dup2(float v){unsigned long long r;asm("mov.b64 %0,{%1,%1};":"=l"(r):"f"(v));return r;}
__device__ __forceinline__ unsigned long long pk2(float a,float b){unsigned long long r;asm("mov.b64 %0,{%1,%2};":"=l"(r):"f"(a),"f"(b));return r;}
__device__ __forceinline__ unsigned long long fma2(unsigned long long a,unsigned long long b,unsigned long long c){unsigned long long d;asm("fma.rn.f32x2 %0,%1,%2,%3;":"=l"(d):"l"(a),"l"(b),"l"(c));return d;}
__device__ __forceinline__ unsigned long long add2(unsigned long long a,unsigned long long b){unsigned long long d;asm("add.rn.f32x2 %0,%1,%2;":"=l"(d):"l"(a),"l"(b));return d;}
__device__ __forceinline__ float2 unp2(unsigned long long v){float2 f;asm("mov.b64 {%0,%1},%2;":"=f"(f.x),"=f"(f.y):"l"(v));return f;}

#if TC_ON
__device__ __forceinline__ bool elect_one(){uint32_t p;asm volatile("{\n\t.reg .pred P;\n\telect.sync _|P,0xFFFFFFFF;\n\tselp.b32 %0,1,0,P;\n\t}":"=r"(p));return p!=0;}
__device__ __forceinline__ void mbar_init(uint32_t b,uint32_t c){asm volatile("mbarrier.init.shared.b64 [%0],%1;"::"r"(b),"r"(c):"memory");}
__device__ __forceinline__ void mbar_expect(uint32_t b,uint32_t n){asm volatile("mbarrier.arrive.expect_tx.shared.b64 _,[%0],%1;"::"r"(b),"r"(n):"memory");}
__device__ __forceinline__ void mbar_arrive(uint32_t b){asm volatile("mbarrier.arrive.shared.b64 _,[%0];"::"r"(b):"memory");}
__device__ __forceinline__ void mbar_wait(uint32_t b,uint32_t p){
    asm volatile("{\n\t.reg .pred P;\nWL%=:\n\tmbarrier.try_wait.parity.acquire.cta.shared::cta.b64 P,[%0],%1,0x989680;\n\t@P bra WD%=;\n\tbra WL%=;\nWD%=:\n\t}"::"r"(b),"r"(p):"memory");}
__device__ __forceinline__ void bulk_cp(uint32_t d,const void* s,uint32_t n,uint32_t b){
    asm volatile("cp.async.bulk.shared::cluster.global.mbarrier::complete_tx::bytes [%0],[%1],%2,[%3];"::"r"(d),"l"(s),"r"(n),"r"(b):"memory");}
__device__ __forceinline__ uint64_t desc64(uint32_t a){
    const uint64_t base=(4ULL<<61)|(1ULL<<46)|(32ULL<<32)|(1ULL<<16);
    return base | (uint64_t)((a>>4)&0x3FFF);}
__device__ __forceinline__ void mma_ss(uint32_t d,uint64_t a,uint64_t b,uint32_t en){
    asm volatile("{\n\t.reg .pred p;\n\tsetp.ne.u32 p,%4,0;\n\ttcgen05.mma.cta_group::1.kind::f16 [%0],%1,%2,%3,{%5,%5,%5,%5},p;\n\t}"::"r"(d),"l"(a),"l"(b),"r"(IDESC),"r"(en),"r"(0u):"memory");}
__device__ __forceinline__ void tc_commit(uint32_t b){asm volatile("tcgen05.commit.cta_group::1.mbarrier::arrive::one.shared::cluster.b64 [%0];"::"r"(b):"memory");}
__device__ __forceinline__ void ldtm8(uint32_t* r,uint32_t a){
    asm volatile("tcgen05.ld.sync.aligned.32x32b.x8.b32 {%0,%1,%2,%3,%4,%5,%6,%7},[%8];"
    :"=r"(r[0]),"=r"(r[1]),"=r"(r[2]),"=r"(r[3]),"=r"(r[4]),"=r"(r[5]),"=r"(r[6]),"=r"(r[7]):"r"(a));}
__device__ __forceinline__ void tc_wait_ld(){asm volatile("tcgen05.wait::ld.sync.aligned;":::"memory");}
__device__ __forceinline__ void tc_fb(){asm volatile("tcgen05.fence::before_thread_sync;":::"memory");}
__device__ __forceinline__ void tc_fa(){asm volatile("tcgen05.fence::after_thread_sync;":::"memory");}

// expand one 32-int8 row -> 16 fp16x2 into SW64 lo tile, scale baked in
__device__ __forceinline__ void expand_row(uint32_t qa,uint32_t la,int r,uint32_t s2){
    uint32_t d0,d1,d2,d3,d4,d5,d6,d7;
    uint32_t src=qa+r*32;
    asm volatile("ld.shared.v4.u32 {%0,%1,%2,%3},[%4];":"=r"(d0),"=r"(d1),"=r"(d2),"=r"(d3):"r"(src));
    asm volatile("ld.shared.v4.u32 {%0,%1,%2,%3},[%4];":"=r"(d4),"=r"(d5),"=r"(d6),"=r"(d7):"r"(src+16));
    uint32_t dd[8]={d0,d1,d2,d3,d4,d5,d6,d7};
    uint32_t o[16];
    __half2 s=*(__half2*)&s2;
#pragma unroll
    for(int i=0;i<8;++i){
        int b0,b1,b2,b3;
        asm("dp4a.s32.s32 %0,%1,%2,%3;":"=r"(b0):"r"(dd[i]),"r"(1),"r"(0));
        asm("dp4a.s32.s32 %0,%1,%2,%3;":"=r"(b1):"r"(dd[i]),"r"(0x100),"r"(0));
        asm("dp4a.s32.s32 %0,%1,%2,%3;":"=r"(b2):"r"(dd[i]),"r"(0x10000),"r"(0));
        asm("dp4a.s32.s32 %0,%1,%2,%3;":"=r"(b3):"r"(dd[i]),"r"(0x1000000),"r"(0));
        __half2 h01=__hmul2(__floats2half2_rn((float)b0,(float)b1),s);
        __half2 h23=__hmul2(__floats2half2_rn((float)b2,(float)b3),s);
        o[2*i]=*(uint32_t*)&h01; o[2*i+1]=*(uint32_t*)&h23;
    }
    uint32_t rb=(uint32_t)r*64;
#pragma unroll
    for(int j=0;j<4;++j){
        uint32_t a=la+swz64(rb+j*16);
        asm volatile("st.shared.v4.b32 [%0],{%1,%2,%3,%4};"::"r"(a),"r"(o[4*j]),"r"(o[4*j+1]),"r"(o[4*j+2]),"r"(o[4*j+3]):"memory");
    }
}
#endif

// ---------------------------------------------------------------------------
// Pack: fp32 [rows,4096] -> per 128x32 tile: fp16 hi (SW64 8K) + int8 q (4K)
__global__ void __launch_bounds__(256)
pack_kernel(const float* __restrict__ src, uint8_t* __restrict__ dst, int rows, float qs){
#if TC_ON
    int idx=blockIdx.x*blockDim.x+threadIdx.x;
    int kq=idx&(K_DIM/8-1);
    int row=idx>>9;
    if(row>=rows) return;
    const float4* s=(const float4*)(src+(size_t)row*K_DIM+kq*8);
    float4 v0=s[0],v1=s[1];
    float f[8]={v0.x,v0.y,v0.z,v0.w,v1.x,v1.y,v1.z,v1.w};
    uint32_t hi[4]; int q[8];
#pragma unroll
    for(int i=0;i<4;++i){
        __half h0=__float2half_rn(f[2*i]),h1=__float2half_rn(f[2*i+1]);
        float l0=f[2*i]-__half2float(h0), l1=f[2*i+1]-__half2float(h1);
        hi[i]=(uint32_t)__half_as_ushort(h0)|((uint32_t)__half_as_ushort(h1)<<16);
        q[2*i]  =(int)fminf(fmaxf(rintf(l0*qs),-127.f),127.f);
        q[2*i+1]=(int)fminf(fmaxf(rintf(l1*qs),-127.f),127.f);
    }
    uint32_t p0=(q[0]&0xFF)|((q[1]&0xFF)<<8)|((q[2]&0xFF)<<16)|((q[3]&0xFF)<<24);
    uint32_t p1=(q[4]&0xFF)|((q[5]&0xFF)<<8)|((q[6]&0xFF)<<16)|((q[7]&0xFF)<<24);
    int rb=row>>7, r=row&127, k=kq*8, kb=k>>5, c=k&31;
    size_t tb=((size_t)rb*KB_TILES+kb)*TILE_PK;
    *(uint4*)(dst+tb+swz64((uint32_t)(r*64+c*2)))=make_uint4(hi[0],hi[1],hi[2],hi[3]);
    *(uint2*)(dst+tb+8192+r*32+c)=make_uint2(p0,p1);
#else
    (void)src;(void)dst;(void)rows;(void)qs;
#endif
}

// ---------------------------------------------------------------------------
__global__ void __launch_bounds__(THREADS,1)
vmm_main_kernel(const float* __restrict__ x,const float* __restrict__ w,
                const float* __restrict__ bias,float* __restrict__ out){
    extern __shared__ uint8_t dyn[];
#if TC_ON
    __shared__ __align__(8) uint64_t s_fullRaw[NSTAGE],s_fullExp[NSTAGE],s_empty[NSTAGE];
    __shared__ __align__(8) uint64_t s_mma_done[2],s_epi_done[2];
    __shared__ uint32_t s_tmem_ptr;
    const uint32_t sbase=(smem_u32(dyn)+1023)&~1023u;
    const int tid=threadIdx.x, wid=tid>>5, lane=tid&31;
    const int nblk=blockIdx.x, mblk=blockIdx.y;
    const int n0=nblk*BN, m0=mblk*256;

    if(tid==0){
#pragma unroll
        for(int s=0;s<NSTAGE;++s){
            mbar_init(smem_u32(&s_fullRaw[s]),1);
            mbar_init(smem_u32(&s_fullExp[s]),128);
            mbar_init(smem_u32(&s_empty[s]),1);
        }
        mbar_init(smem_u32(&s_mma_done[0]),1); mbar_init(smem_u32(&s_mma_done[1]),1);
        mbar_init(smem_u32(&s_epi_done[0]),512); mbar_init(smem_u32(&s_epi_done[1]),512);
    }
    if(wid==MMA_WARP)
        asm volatile("tcgen05.alloc.cta_group::1.sync.aligned.shared::cta.b32 [%0],%1;"::"r"(smem_u32(&s_tmem_ptr)),"r"(512u):"memory");
    __syncthreads();
    const uint32_t tmem=s_tmem_ptr;

    if(wid==PROD_WARP){
        if(elect_one()){
            const uint8_t* a0=g_xpack+((size_t)(mblk*2+0)*KB_TILES)*TILE_PK;
            const uint8_t* a1=g_xpack+((size_t)(mblk*2+1)*KB_TILES)*TILE_PK;
            const uint8_t* bb=g_wpack+((size_t)nblk*KB_TILES)*TILE_PK;
            int ph[NSTAGE]={1,1,1}; int st=0;
            for(int s=0;s<NSS;++s){
                mbar_wait(smem_u32(&s_empty[st]),ph[st]); ph[st]^=1;
                uint32_t d=sbase+st*STAGE, fb=smem_u32(&s_fullRaw[st]);
                mbar_expect(fb,RAW_TX);
                bulk_cp(d,       a0+(size_t)s*TILE_PK,TILE_PK,fb);
                bulk_cp(d+12288, a1+(size_t)s*TILE_PK,TILE_PK,fb);
                bulk_cp(d+24576, bb+(size_t)s*TILE_PK,TILE_PK,fb);
                st=st+1==NSTAGE?0:st+1;
            }
        }
    } else if(wid==MMA_WARP){
        if(elect_one()){
            int fph[NSTAGE]={0,0,0}; int eph[2]={1,1}; int st=0;
            for(int c=0;c<NCHUNK;++c){
                int slot=c&1;
                mbar_wait(smem_u32(&s_epi_done[slot]),eph[slot]); eph[slot]^=1;
                tc_fa();
                uint32_t d0=tmem+(slot*2+0)*128, d1=tmem+(slot*2+1)*128;
                for(int sub=0;sub<4;++sub){
                    mbar_wait(smem_u32(&s_fullExp[st]),fph[st]); fph[st]^=1;
                    uint32_t a=sbase+st*STAGE;
                    uint64_t A0h=desc64(a), A1h=desc64(a+12288), Bh=desc64(a+24576);
                    uint64_t A0l=desc64(a+OFF_A0L), A1l=desc64(a+OFF_A1L), Bl=desc64(a+OFF_BL);
                    uint64_t t0a[3]={A0h,A0l,A0h}, t1a[3]={A1h,A1l,A1h}, tb[3]={Bh,Bh,Bl};
#pragma unroll
                    for(int t=0;t<3;++t)
#pragma unroll
                        for(int ks=0;ks<2;++ks){
                            uint32_t en=!(sub==0&&t==0&&ks==0);
                            mma_ss(d0,t0a[t]+ks*2,tb[t]+ks*2,en);
                            mma_ss(d1,t1a[t]+ks*2,tb[t]+ks*2,en);
                        }
                    tc_commit(smem_u32(&s_empty[st]));
                    st=st+1==NSTAGE?0:st+1;
                }
                tc_commit(smem_u32(&s_mma_done[slot]));
            }
        }
    } else if(wid>=18){
        // ---- expansion warps: int8 -> fp16*scale into SW64 lo tiles ----
        const int e=tid-576;            // 0..127
        __half2 tA=__float2half2_rn(0x1p-19f), tB=__float2half2_rn(0x1p-16f);
        uint32_t s2A=*(uint32_t*)&tA, s2B=*(uint32_t*)&tB;
        int ph[NSTAGE]={0,0,0}; int st=0;
        for(int s=0;s<NSS;++s){
            mbar_wait(smem_u32(&s_fullRaw[st]),ph[st]); ph[st]^=1;
            uint32_t sb=sbase+st*STAGE;
            expand_row(sb+8192, sb+OFF_A0L,e,s2A);
            expand_row(sb+20480,sb+OFF_A1L,e,s2A);
            expand_row(sb+32768,sb+OFF_BL, e,s2B);
            asm volatile("fence.proxy.async.shared::cta;":::"memory");
            mbar_arrive(smem_u32(&s_fullExp[st]));
            st=st+1==NSTAGE?0:st+1;
        }
    } else {
        // ---- epilogue: 16 warps; wid = msub*8 + grp*4 + sp ----
        const int msub=wid>>3, grp=(wid>>2)&1, sp=wid&3;
        unsigned long long racc2[32];
#pragma unroll
        for(int i=0;i<32;++i) racc2[i]=0ULL;
        const unsigned long long S2=dup2(99.609375f), M2=dup2(MAGIC),
                                 NM2=dup2(-MAGIC),   I2=dup2(2.56f/255.0f);
        int mph[2]={0,0};
        for(int c=0;c<NCHUNK;++c){
            int slot=c&1;
            mbar_wait(smem_u32(&s_mma_done[slot]),mph[slot]); mph[slot]^=1;
            tc_fa();
            uint32_t base=tmem+(slot*2+msub)*128+grp*64;
#pragma unroll
            for(int b=0;b<8;++b){
                uint32_t dr[8];
                ldtm8(dr,base+b*8);
                tc_wait_ld();
#pragma unroll
                for(int j=0;j<8;j+=2){
                    float f0=__uint_as_float(dr[j]), f1=__uint_as_float(dr[j+1]);
                    float y0=fminf(fmaxf(f0,-2.56f),2.56f);
                    float y1=fminf(fmaxf(f1,-2.56f),2.56f);
                    unsigned long long Y=pk2(y0,y1);
                    unsigned long long T=fma2(Y,S2,M2);
                    unsigned long long Q=add2(T,NM2);
                    racc2[4*b+(j>>1)]=fma2(Q,I2,racc2[4*b+(j>>1)]);
                }
            }
            tc_fb();
            mbar_arrive(smem_u32(&s_epi_done[slot]));
        }
        const int m=m0+msub*128+sp*32+lane;
        const float* bp=bias+n0+grp*64;
        float* op=out+(size_t)m*N_DIM+n0+grp*64;
#pragma unroll
        for(int q=0;q<16;++q){
            float2 a=unp2(racc2[2*q]), b=unp2(racc2[2*q+1]);
            float4 bb=*(const float4*)(bp+q*4);
            float4 o; o.x=a.x+bb.x; o.y=a.y+bb.y; o.z=b.x+bb.z; o.w=b.y+bb.w;
            *(float4*)(op+q*4)=o;
        }
    }

    __syncthreads();
    if(wid==MMA_WARP){
        asm volatile("tcgen05.relinquish_alloc_permit.cta_group::1.sync.aligned;");
        asm volatile("tcgen05.dealloc.cta_group::1.sync.aligned.b32 %0,%1;"::"r"(tmem),"r"(512u));
    }
#else
    // plain-sm_103 fallback (never executes; sm_103a cubin is loaded)
    size_t total=(size_t)8192*N_DIM;
    size_t stride=(size_t)gridDim.x*gridDim.y*blockDim.x;
    size_t gid=((size_t)blockIdx.y*gridDim.x+blockIdx.x)*blockDim.x+threadIdx.x;
    for(size_t i=gid;i<total;i+=stride){
        int m=(int)(i/N_DIM), n=(int)(i%N_DIM);
        float acc=0.0f;
        for(int c=0;c<32;++c){
            float p=0.0f;
            for(int k=0;k<128;++k)
                p+=x[(size_t)m*K_DIM+c*128+k]*w[(size_t)n*K_DIM+c*128+k];
            float y=fminf(fmaxf(p,-2.56f),2.56f)*(255.0f/2.56f);
            acc+=rintf(y)*(2.56f/255.0f);
        }
        out[i]=acc+bias[n];
    }
    (void)dyn;
#endif
}

// ---------------------------------------------------------------------------
extern "C" void kernel_launch(void* const* d_in,const int* in_sizes,int n_in,
                              void* d_out,int out_size){
    const float* x   =(const float*)d_in[0];
    const float* w   =(const float*)d_in[1];
    const float* bias=(const float*)d_in[2];
    float* out=(float*)d_out;
    const int Bdim=in_sizes[0]/K_DIM;   // 8192

    uint8_t* xp=nullptr; uint8_t* wp=nullptr;
    cudaGetSymbolAddress((void**)&xp,g_xpack);
    cudaGetSymbolAddress((void**)&wp,g_wpack);

    cudaFuncSetAttribute(vmm_main_kernel,cudaFuncAttributeMaxDynamicSharedMemorySize,DYN_BYTES);

    pack_kernel<<<Bdim*2,256>>>(x,xp,Bdim,524288.0f);   // 2^19
    pack_kernel<<<N_DIM*2,256>>>(w,wp,N_DIM,65536.0f);  // 2^16

    dim3 grid(N_DIM/BN,Bdim/256);       // (32, 32)
    vmm_main_kernel<<<grid,THREADS,DYN_BYTES>>>(x,w,bias,out);
}

// round 17
// speedup vs baseline: 1.4627x; 1.4627x over previous
#include <cuda_runtime.h>
#include <cuda_bf16.h>
#include <cstdint>

// ============================================================================
// HardwareVMMoperation: out = sum_{c<32} Q(x[:,128c:+128] @ W[:,128c:+128]^T) + bias
// B=8192, K=N=4096 fp32.  Q = clamp(+-2.56) -> *(255/2.56) -> rint -> back.
//
// tcgen05 bf16 3-term split GEMM, BM=256, BN=128, KSUB=32, SW64 tiles,
// 4-stage bulk-copy pipeline, TMEM ping-pong, 16 epi warps.
// cluster-2 along n; A (x) tiles delivered by multicast bulk copy;
// stage-empty barriers count=2 signalled by commit-multicast from both CTAs.
// (This is the proven 551.8us kernel; epilogue rint -> FMA magic round.)
//   - sm_103a pass: tcgen05 path;  plain sm_103 pass: FFMA2 fallback.
// ============================================================================

#if defined(__CUDA_ARCH__) && defined(__CUDA_ARCH_FEAT_SM103_ALL)
#define TC_ON 1
#else
#define TC_ON 0
#endif

#define K_DIM   4096
#define N_DIM   4096
#define BM      256                // per CTA (2 m-subtiles of 128)
#define BN      128
#define KSUB    32
#define NSTAGE  4
#define TILE_B  8192               // 128 rows x 32 k x 2B, SW64-swizzled
#define TPAIR   (2 * TILE_B)       // hi + lo = 16384
#define STAGE_BYTES (3 * TPAIR)    // A0 pair, A1 pair, B pair = 49152
#define NSS     (K_DIM / KSUB)     // 128
#define SUBS_PER_CHUNK 4
#define NCHUNK  32
#define THREADS 576
#define MMA_WARP  16
#define PROD_WARP 17
#define IDESC   0x8200490u
#define DYN_BYTES (NSTAGE * STAGE_BYTES + 1024)
#define CL_MASK 0x3                // both cluster CTAs
#define MAGIC   12582912.0f        // 2^23 + 2^22

#define KB_TILES (K_DIM / KSUB)    // 128
#define X_ROWTILES (8192 / 128)    // 64
#define W_ROWTILES (N_DIM / 128)   // 32

__device__ __align__(128) uint8_t g_xpack[(size_t)X_ROWTILES * KB_TILES * TPAIR];
__device__ __align__(128) uint8_t g_wpack[(size_t)W_ROWTILES * KB_TILES * TPAIR];

// ---------------------------------------------------------------------------
__device__ __forceinline__ uint32_t smem_u32(const void* p) {
    return (uint32_t)__cvta_generic_to_shared(p);
}

#if TC_ON
// ---------------------------------------------------------------------------
__device__ __forceinline__ bool elect_one() {
    uint32_t p;
    asm volatile("{\n\t.reg .pred P;\n\telect.sync _|P, 0xFFFFFFFF;\n\t"
                 "selp.b32 %0, 1, 0, P;\n\t}" : "=r"(p));
    return p != 0;
}
__device__ __forceinline__ uint32_t ctarank() {
    uint32_t r;
    asm("mov.u32 %0, %%cluster_ctarank;" : "=r"(r));
    return r;
}
__device__ __forceinline__ void cluster_sync_all() {
    asm volatile("barrier.cluster.arrive.aligned;" ::: "memory");
    asm volatile("barrier.cluster.wait.aligned;" ::: "memory");
}
__device__ __forceinline__ void mbar_init(uint32_t bar, uint32_t cnt) {
    asm volatile("mbarrier.init.shared.b64 [%0], %1;" :: "r"(bar), "r"(cnt) : "memory");
}
__device__ __forceinline__ void mbar_expect_tx(uint32_t bar, uint32_t bytes) {
    asm volatile("mbarrier.arrive.expect_tx.shared.b64 _, [%0], %1;"
                 :: "r"(bar), "r"(bytes) : "memory");
}
__device__ __forceinline__ void mbar_arrive(uint32_t bar) {
    asm volatile("mbarrier.arrive.shared.b64 _, [%0];" :: "r"(bar) : "memory");
}
__device__ __forceinline__ void mbar_wait(uint32_t bar, uint32_t parity) {
    asm volatile("{\n\t.reg .pred P;\n"
        "WL%=:\n\t"
        "mbarrier.try_wait.parity.acquire.cta.shared::cta.b64 P, [%0], %1, 0x989680;\n\t"
        "@P bra WD%=;\n\t"
        "bra WL%=;\n"
        "WD%=:\n\t}"
        :: "r"(bar), "r"(parity) : "memory");
}
__device__ __forceinline__ void bulk_cp(uint32_t dst, const void* src, uint32_t bytes,
                                        uint32_t bar) {
    asm volatile("cp.async.bulk.shared::cluster.global.mbarrier::complete_tx::bytes "
                 "[%0], [%1], %2, [%3];"
                 :: "r"(dst), "l"(src), "r"(bytes), "r"(bar) : "memory");
}
__device__ __forceinline__ void bulk_cp_mcast(uint32_t dst, const void* src, uint32_t bytes,
                                              uint32_t bar, uint16_t mask) {
    asm volatile("cp.async.bulk.shared::cluster.global.mbarrier::complete_tx::bytes"
                 ".multicast::cluster [%0], [%1], %2, [%3], %4;"
                 :: "r"(dst), "l"(src), "r"(bytes), "r"(bar), "h"(mask) : "memory");
}
// SW64 K-major descriptor: layout=4, version=1, SBO=32, LBO=1
__device__ __forceinline__ uint64_t make_desc64(uint32_t addr) {
    const uint64_t base = (4ULL << 61) | (1ULL << 46) | (32ULL << 32) | (1ULL << 16);
    return base | (uint64_t)((addr >> 4) & 0x3FFF);
}
__device__ __forceinline__ void mma_ss(uint32_t d, uint64_t a, uint64_t b, uint32_t en) {
    asm volatile("{\n\t.reg .pred p;\n\tsetp.ne.u32 p, %4, 0;\n\t"
        "tcgen05.mma.cta_group::1.kind::f16 [%0], %1, %2, %3, {%5, %5, %5, %5}, p;\n\t}"
        :: "r"(d), "l"(a), "l"(b), "r"(IDESC), "r"(en), "r"(0u) : "memory");
}
__device__ __forceinline__ void tc_commit(uint32_t bar) {
    asm volatile("tcgen05.commit.cta_group::1.mbarrier::arrive::one.shared::cluster.b64 [%0];"
                 :: "r"(bar) : "memory");
}
__device__ __forceinline__ void tc_commit_mcast(uint32_t bar, uint16_t mask) {
    asm volatile("tcgen05.commit.cta_group::1.mbarrier::arrive::one.shared::cluster"
                 ".multicast::cluster.b64 [%0], %1;"
                 :: "r"(bar), "h"(mask) : "memory");
}
__device__ __forceinline__ void ldtm16(uint32_t* r, uint32_t addr) {
    asm volatile("tcgen05.ld.sync.aligned.32x32b.x16.b32 "
        "{%0,%1,%2,%3,%4,%5,%6,%7,%8,%9,%10,%11,%12,%13,%14,%15}, [%16];"
        : "=r"(r[0]), "=r"(r[1]), "=r"(r[2]), "=r"(r[3]),
          "=r"(r[4]), "=r"(r[5]), "=r"(r[6]), "=r"(r[7]),
          "=r"(r[8]), "=r"(r[9]), "=r"(r[10]), "=r"(r[11]),
          "=r"(r[12]), "=r"(r[13]), "=r"(r[14]), "=r"(r[15])
        : "r"(addr));
}
__device__ __forceinline__ void tc_wait_ld()      { asm volatile("tcgen05.wait::ld.sync.aligned;" ::: "memory"); }
__device__ __forceinline__ void tc_fence_before() { asm volatile("tcgen05.fence::before_thread_sync;" ::: "memory"); }
__device__ __forceinline__ void tc_fence_after()  { asm volatile("tcgen05.fence::after_thread_sync;" ::: "memory"); }
#else
__device__ __forceinline__ unsigned long long dup2(float v) {
    unsigned long long r;
    asm("mov.b64 %0, {%1, %1};" : "=l"(r) : "f"(v));
    return r;
}
__device__ __forceinline__ void ffma2(unsigned long long &d,
                                      unsigned long long a, unsigned long long b) {
    asm("fma.rn.f32x2 %0, %1, %2, %0;" : "+l"(d) : "l"(a), "l"(b));
}
__device__ __forceinline__ float2 unpack2(unsigned long long v) {
    float2 f;
    asm("mov.b64 {%0, %1}, %2;" : "=f"(f.x), "=f"(f.y) : "l"(v));
    return f;
}
__device__ __forceinline__ float quantize_partial(float p) {
    float y = fminf(fmaxf(p, -2.56f), 2.56f);
    y = y * (255.0f / 2.56f);
    y = rintf(y);
    return y * (2.56f / 255.0f);
}
#endif

// ---------------------------------------------------------------------------
// Pre-pass: fp32 [rows,4096] -> hi/lo bf16, SW64-swizzled 128x32 tiles.
// ---------------------------------------------------------------------------
__global__ void __launch_bounds__(256)
pack_kernel(const float* __restrict__ src, uint8_t* __restrict__ dst, int rows) {
#if TC_ON
    int idx = blockIdx.x * blockDim.x + threadIdx.x;   // one thread = 8 k's
    int kq  = idx & (K_DIM / 8 - 1);
    int row = idx >> 9;
    if (row >= rows) return;

    const float4* s = (const float4*)(src + (size_t)row * K_DIM + kq * 8);
    float4 v0 = s[0], v1 = s[1];
    float f[8] = {v0.x, v0.y, v0.z, v0.w, v1.x, v1.y, v1.z, v1.w};

    uint32_t hi[4], lo[4];
#pragma unroll
    for (int i = 0; i < 4; ++i) {
        __nv_bfloat16 h0 = __float2bfloat16_rn(f[2 * i]);
        __nv_bfloat16 h1 = __float2bfloat16_rn(f[2 * i + 1]);
        __nv_bfloat16 l0 = __float2bfloat16_rn(f[2 * i]     - __bfloat162float(h0));
        __nv_bfloat16 l1 = __float2bfloat16_rn(f[2 * i + 1] - __bfloat162float(h1));
        hi[i] = (uint32_t)__bfloat16_as_ushort(h0) | ((uint32_t)__bfloat16_as_ushort(h1) << 16);
        lo[i] = (uint32_t)__bfloat16_as_ushort(l0) | ((uint32_t)__bfloat16_as_ushort(l1) << 16);
    }

    int rb = row >> 7, r = row & 127;
    int k  = kq * 8;
    int kb = k >> 5;
    int c  = k & 31;
    uint32_t off = (uint32_t)(r * 64 + c * 2);
    off ^= (off >> 3) & 0x30;        // SW64 swizzle
    size_t tbase = ((size_t)rb * KB_TILES + kb) * TPAIR;
    *(uint4*)(dst + tbase + off)          = make_uint4(hi[0], hi[1], hi[2], hi[3]);
    *(uint4*)(dst + tbase + TILE_B + off) = make_uint4(lo[0], lo[1], lo[2], lo[3]);
#else
    (void)src; (void)dst; (void)rows;
#endif
}

// ---------------------------------------------------------------------------
// Main kernel: grid (N/128, B/256), cluster (2,1,1), 576 threads
// ---------------------------------------------------------------------------
__global__ void __launch_bounds__(THREADS, 1) __cluster_dims__(2, 1, 1)
vmm_main_kernel(const float* __restrict__ x, const float* __restrict__ w,
                const float* __restrict__ bias, float* __restrict__ out) {
    extern __shared__ uint8_t dyn[];
#if TC_ON
    // ======================= tcgen05 path =======================
    __shared__ __align__(8) uint64_t s_full[NSTAGE], s_empty[NSTAGE];
    __shared__ __align__(8) uint64_t s_mma_done[2], s_epi_done[2];
    __shared__ uint32_t s_tmem_ptr;

    const uint32_t sbase = (smem_u32(dyn) + 1023) & ~1023u;
    const int tid  = threadIdx.x;
    const int wid  = tid >> 5;
    const int lane = tid & 31;
    const int nblk = blockIdx.x, mblk = blockIdx.y;
    const int n0 = nblk * BN, m0 = mblk * BM;
    const uint32_t rank = ctarank();   // 0/1 within n-pair

    if (tid == 0) {
#pragma unroll
        for (int s = 0; s < NSTAGE; ++s) {
            mbar_init(smem_u32(&s_full[s]), 1);
            mbar_init(smem_u32(&s_empty[s]), 2);   // both CTAs' MMA warps arrive
        }
        mbar_init(smem_u32(&s_mma_done[0]), 1);
        mbar_init(smem_u32(&s_mma_done[1]), 1);
        mbar_init(smem_u32(&s_epi_done[0]), 512);
        mbar_init(smem_u32(&s_epi_done[1]), 512);
    }
    if (wid == MMA_WARP) {
        asm volatile("tcgen05.alloc.cta_group::1.sync.aligned.shared::cta.b32 [%0], %1;"
                     :: "r"(smem_u32(&s_tmem_ptr)), "r"(512u) : "memory");
    }
    __syncthreads();
    cluster_sync_all();               // peer barriers visible before any multicast
    const uint32_t tmem = s_tmem_ptr;

    if (wid == PROD_WARP) {
        // ---- producer: rank0 multicasts A pair to both CTAs; each loads its B ----
        if (elect_one()) {
            const uint8_t* a0src = g_xpack + ((size_t)(mblk * 2 + 0) * KB_TILES) * TPAIR;
            const uint8_t* a1src = g_xpack + ((size_t)(mblk * 2 + 1) * KB_TILES) * TPAIR;
            const uint8_t* bsrc  = g_wpack + ((size_t)nblk * KB_TILES) * TPAIR;
            int eph[NSTAGE] = {1, 1, 1, 1};
            for (int s = 0; s < NSS; ++s) {
                int st = s & (NSTAGE - 1);
                mbar_wait(smem_u32(&s_empty[st]), eph[st]); eph[st] ^= 1;
                uint32_t d = sbase + st * STAGE_BYTES;
                uint32_t fb = smem_u32(&s_full[st]);
                mbar_expect_tx(fb, STAGE_BYTES);
                if (rank == 0) {
                    bulk_cp_mcast(d,         a0src + (size_t)s * TPAIR, TPAIR, fb, CL_MASK);
                    bulk_cp_mcast(d + TPAIR, a1src + (size_t)s * TPAIR, TPAIR, fb, CL_MASK);
                }
                bulk_cp(d + 2 * TPAIR, bsrc + (size_t)s * TPAIR, TPAIR, fb);
            }
        }
    } else if (wid == MMA_WARP) {
        // ---- MMA: per chunk, 4 subs x 2 m-subtiles x 3 terms x 2 k-steps ----
        if (elect_one()) {
            int fph[NSTAGE] = {0, 0, 0, 0};
            int eph[2] = {1, 1};
            int st = 0;
            for (int c = 0; c < NCHUNK; ++c) {
                int slot = c & 1;
                mbar_wait(smem_u32(&s_epi_done[slot]), eph[slot]); eph[slot] ^= 1;
                tc_fence_after();
                uint32_t d0 = tmem + (slot * 2 + 0) * 128;
                uint32_t d1 = tmem + (slot * 2 + 1) * 128;
                for (int sub = 0; sub < SUBS_PER_CHUNK; ++sub) {
                    mbar_wait(smem_u32(&s_full[st]), fph[st]); fph[st] ^= 1;
                    uint32_t a = sbase + st * STAGE_BYTES;
                    uint64_t A0h = make_desc64(a);
                    uint64_t A0l = make_desc64(a + TILE_B);
                    uint64_t A1h = make_desc64(a + TPAIR);
                    uint64_t A1l = make_desc64(a + TPAIR + TILE_B);
                    uint64_t Bh  = make_desc64(a + 2 * TPAIR);
                    uint64_t Bl  = make_desc64(a + 2 * TPAIR + TILE_B);
                    uint64_t t0a[3] = {A0h, A0l, A0h};
                    uint64_t t1a[3] = {A1h, A1l, A1h};
                    uint64_t tb[3]  = {Bh,  Bh,  Bl};
#pragma unroll
                    for (int t = 0; t < 3; ++t)
#pragma unroll
                        for (int ks = 0; ks < 2; ++ks) {
                            uint32_t en = !(sub == 0 && t == 0 && ks == 0);
                            mma_ss(d0, t0a[t] + ks * 2, tb[t] + ks * 2, en);
                            mma_ss(d1, t1a[t] + ks * 2, tb[t] + ks * 2, en);
                        }
                    // stage free (in BOTH cluster CTAs) when these MMAs drain
                    tc_commit_mcast(smem_u32(&s_empty[st]), CL_MASK);
                    st = (st + 1) & (NSTAGE - 1);
                }
                tc_commit(smem_u32(&s_mma_done[slot])); // chunk D ready (local)
            }
        }
    } else {
        // ---- epilogue: 16 warps; wid = msub*8 + grp*4 + sp ----
        const int msub = wid >> 3;
        const int grp  = (wid >> 2) & 1;
        const int sp   = wid & 3;
        float racc[64];
#pragma unroll
        for (int i = 0; i < 64; ++i) racc[i] = 0.0f;

        int mph[2] = {0, 0};
        for (int c = 0; c < NCHUNK; ++c) {
            int slot = c & 1;
            mbar_wait(smem_u32(&s_mma_done[slot]), mph[slot]); mph[slot] ^= 1;
            tc_fence_after();
            uint32_t base = tmem + (slot * 2 + msub) * 128 + grp * 64;
#pragma unroll
            for (int b = 0; b < 4; ++b) {
                uint32_t dr[16];
                ldtm16(dr, base + b * 16);
                tc_wait_ld();
#pragma unroll
                for (int j = 0; j < 16; ++j) {
                    // Q(p) via FMA magic-number half-even round (no FRND):
                    float p = __uint_as_float(dr[j]);
                    float y = fminf(fmaxf(p, -2.56f), 2.56f);
                    float t = fmaf(y, 99.609375f, MAGIC);
                    float q = t - MAGIC;                    // rint(y * 255/2.56)
                    racc[b * 16 + j] = fmaf(q, 2.56f / 255.0f, racc[b * 16 + j]);
                }
            }
            tc_fence_before();
            mbar_arrive(smem_u32(&s_epi_done[slot]));
        }

        const int m  = m0 + msub * 128 + sp * 32 + lane;
        const float* bp = bias + n0 + grp * 64;
        float* op = out + (size_t)m * N_DIM + n0 + grp * 64;
#pragma unroll
        for (int q = 0; q < 16; ++q) {
            float4 bb = *(const float4*)(bp + q * 4);
            float4 o;
            o.x = racc[q * 4 + 0] + bb.x;
            o.y = racc[q * 4 + 1] + bb.y;
            o.z = racc[q * 4 + 2] + bb.z;
            o.w = racc[q * 4 + 3] + bb.w;
            *(float4*)(op + q * 4) = o;
        }
    }

    __syncthreads();
    if (wid == MMA_WARP) {
        asm volatile("tcgen05.relinquish_alloc_permit.cta_group::1.sync.aligned;");
        asm volatile("tcgen05.dealloc.cta_group::1.sync.aligned.b32 %0, %1;"
                     :: "r"(tmem), "r"(512u));
    }
    cluster_sync_all();               // no exit while peer multicast in flight
#else
    // ======================= FFMA2 fallback (plain sm_103; never runs) =======
    float* As = (float*)dyn;
    float* Bs = As + 2 * 16 * 128;
#define ASF(b, k, r) As[((b) * 16 + (k)) * 128 + (r)]
#define BSF(b, k, r) Bs[((b) * 16 + (k)) * 128 + (r)]

    const int tid = threadIdx.x;
    const bool act = tid < 256;
    const int tx  = tid & 15;
    const int ty  = (tid >> 4) & 15;
    const int n0  = blockIdx.x * BN;
    const int ldr = (tid >> 2) & 63;
    const int ldq = tid & 3;

    for (int msub = 0; msub < 2; ++msub) {
        const int m0 = (blockIdx.y * 2 + msub) * 128;
        const float* ax = x + (size_t)(m0 + ldr) * K_DIM + ldq * 4;
        const float* bx = w + (size_t)(n0 + ldr) * K_DIM + ldq * 4;

        unsigned long long pacc[4][8];
        float racc[8][8];
#pragma unroll
        for (int i = 0; i < 4; ++i)
#pragma unroll
            for (int j = 0; j < 8; ++j) pacc[i][j] = 0ULL;
#pragma unroll
        for (int i = 0; i < 8; ++i)
#pragma unroll
            for (int j = 0; j < 8; ++j) racc[i][j] = 0.0f;

        __syncthreads();
        if (act) {
            float4 a0 = *(const float4*)(ax);
            float4 a1 = *(const float4*)(ax + (size_t)64 * K_DIM);
            float4 b0 = *(const float4*)(bx);
            float4 b1 = *(const float4*)(bx + (size_t)64 * K_DIM);
            ASF(0, ldq * 4 + 0, ldr) = a0.x;  ASF(0, ldq * 4 + 1, ldr) = a0.y;
            ASF(0, ldq * 4 + 2, ldr) = a0.z;  ASF(0, ldq * 4 + 3, ldr) = a0.w;
            ASF(0, ldq * 4 + 0, ldr + 64) = a1.x;  ASF(0, ldq * 4 + 1, ldr + 64) = a1.y;
            ASF(0, ldq * 4 + 2, ldr + 64) = a1.z;  ASF(0, ldq * 4 + 3, ldr + 64) = a1.w;
            BSF(0, ldq * 4 + 0, ldr) = b0.x;  BSF(0, ldq * 4 + 1, ldr) = b0.y;
            BSF(0, ldq * 4 + 2, ldr) = b0.z;  BSF(0, ldq * 4 + 3, ldr) = b0.w;
            BSF(0, ldq * 4 + 0, ldr + 64) = b1.x;  BSF(0, ldq * 4 + 1, ldr + 64) = b1.y;
            BSF(0, ldq * 4 + 2, ldr + 64) = b1.z;  BSF(0, ldq * 4 + 3, ldr + 64) = b1.w;
        }
        __syncthreads();

        int buf = 0;
        const int NSUB_F = K_DIM / 16;
        for (int s = 0; s < NSUB_F; ++s) {
            float4 a0, a1, b0, b1;
            const bool has_next = (s + 1 < NSUB_F);
            if (act && has_next) {
                const float* ap = ax + (size_t)(s + 1) * 16;
                const float* bp = bx + (size_t)(s + 1) * 16;
                a0 = *(const float4*)(ap);
                a1 = *(const float4*)(ap + (size_t)64 * K_DIM);
                b0 = *(const float4*)(bp);
                b1 = *(const float4*)(bp + (size_t)64 * K_DIM);
            }
            if (act) {
#pragma unroll
                for (int kk = 0; kk < 16; ++kk) {
                    ulonglong2 av0 = *(const ulonglong2*)&ASF(buf, kk, ty * 8);
                    ulonglong2 av1 = *(const ulonglong2*)&ASF(buf, kk, ty * 8 + 4);
                    float4 bv0 = *(const float4*)&BSF(buf, kk, tx * 8);
                    float4 bv1 = *(const float4*)&BSF(buf, kk, tx * 8 + 4);
                    unsigned long long am[4] = {av0.x, av0.y, av1.x, av1.y};
                    unsigned long long bd[8] = {dup2(bv0.x), dup2(bv0.y), dup2(bv0.z), dup2(bv0.w),
                                                dup2(bv1.x), dup2(bv1.y), dup2(bv1.z), dup2(bv1.w)};
#pragma unroll
                    for (int mi = 0; mi < 4; ++mi)
#pragma unroll
                        for (int j = 0; j < 8; ++j)
                            ffma2(pacc[mi][j], am[mi], bd[j]);
                }
                if ((s & 7) == 7) {
#pragma unroll
                    for (int mi = 0; mi < 4; ++mi)
#pragma unroll
                        for (int j = 0; j < 8; ++j) {
                            float2 p = unpack2(pacc[mi][j]);
                            racc[2 * mi + 0][j] += quantize_partial(p.x);
                            racc[2 * mi + 1][j] += quantize_partial(p.y);
                            pacc[mi][j] = 0ULL;
                        }
                }
            }
            if (has_next) {
                const int nb = buf ^ 1;
                if (act) {
                    ASF(nb, ldq * 4 + 0, ldr) = a0.x;  ASF(nb, ldq * 4 + 1, ldr) = a0.y;
                    ASF(nb, ldq * 4 + 2, ldr) = a0.z;  ASF(nb, ldq * 4 + 3, ldr) = a0.w;
                    ASF(nb, ldq * 4 + 0, ldr + 64) = a1.x;  ASF(nb, ldq * 4 + 1, ldr + 64) = a1.y;
                    ASF(nb, ldq * 4 + 2, ldr + 64) = a1.z;  ASF(nb, ldq * 4 + 3, ldr + 64) = a1.w;
                    BSF(nb, ldq * 4 + 0, ldr) = b0.x;  BSF(nb, ldq * 4 + 1, ldr) = b0.y;
                    BSF(nb, ldq * 4 + 2, ldr) = b0.z;  BSF(nb, ldq * 4 + 3, ldr) = b0.w;
                    BSF(nb, ldq * 4 + 0, ldr + 64) = b1.x;  BSF(nb, ldq * 4 + 1, ldr + 64) = b1.y;
                    BSF(nb, ldq * 4 + 2, ldr + 64) = b1.z;  BSF(nb, ldq * 4 + 3, ldr + 64) = b1.w;
                }
                __syncthreads();
                buf = nb;
            }
        }

        if (act) {
            const float* bptr = bias + n0 + tx * 8;
            float4 bb0 = *(const float4*)(bptr);
            float4 bb1 = *(const float4*)(bptr + 4);
#pragma unroll
            for (int r = 0; r < 8; ++r) {
                float* op = out + (size_t)(m0 + ty * 8 + r) * N_DIM + n0 + tx * 8;
                float4 o0, o1;
                o0.x = racc[r][0] + bb0.x;  o0.y = racc[r][1] + bb0.y;
                o0.z = racc[r][2] + bb0.z;  o0.w = racc[r][3] + bb0.w;
                o1.x = racc[r][4] + bb1.x;  o1.y = racc[r][5] + bb1.y;
                o1.z = racc[r][6] + bb1.z;  o1.w = racc[r][7] + bb1.w;
                *(float4*)(op)     = o0;
                *(float4*)(op + 4) = o1;
            }
        }
    }
#undef ASF
#undef BSF
#endif
}

// ---------------------------------------------------------------------------
extern "C" void kernel_launch(void* const* d_in, const int* in_sizes, int n_in,
                              void* d_out, int out_size) {
    const float* x    = (const float*)d_in[0];
    const float* w    = (const float*)d_in[1];
    const float* bias = (const float*)d_in[2];
    float* out = (float*)d_out;

    const int Bdim = in_sizes[0] / K_DIM;   // 8192

    uint8_t* xpack = nullptr; uint8_t* wpack = nullptr;
    cudaGetSymbolAddress((void**)&xpack, g_xpack);
    cudaGetSymbolAddress((void**)&wpack, g_wpack);

    cudaFuncSetAttribute(vmm_main_kernel,
                         cudaFuncAttributeMaxDynamicSharedMemorySize, DYN_BYTES);

    pack_kernel<<<Bdim * 2, 256>>>(x, xpack, Bdim);
    pack_kernel<<<N_DIM * 2, 256>>>(w, wpack, N_DIM);

    dim3 grid(N_DIM / BN, Bdim / BM);       // (32, 32)
    vmm_main_kernel<<<grid, THREADS, DYN_BYTES>>>(x, w, bias, out);
}